// round 13
// baseline (speedup 1.0000x reference)
#include <cuda_runtime.h>
#include <cuda_fp16.h>
#include <cstdint>

#define THREADS 512
#define NTILES  2048          // 131072 / 64 rows

#define ISF   0.08838834764831845f
#define IS3   0.5773502691896258f
#define LOG2E 1.4426950408889634f

// ---------------- smem byte offsets ----------------
// two slice buffers (fp16): each 5 slices (X0..X3, E) x 8KB = 40KB
#define OFF_SL   0u
#define SLBUF    40960u
#define OFF_W0A  81920u       // W0[0:64,:]^T  [o:128][k:64] fp16, 16KB
#define OFF_W0B  98304u       // W0[64:128,:]^T
#define OFF_W1A  114688u      // W1[0:64,:]^T  [o:64][k:64] fp16, 8KB
#define OFF_W1B  122880u      // W1[64:128,:]^T
#define OFF_SCR  131072u      // x staging scratch: 16 warps x 4 rows x 1056B
#define SCR_WARP 4224u
#define SCR_ROW  1056u
#define SMEM_BYTES 198656

__device__ __forceinline__ uint32_t sw128(uint32_t o){ return o ^ ((o >> 3) & 0x70); }
__device__ __forceinline__ uint32_t smem_u32(const void* p){
    uint32_t a;
    asm("{ .reg .u64 t; cvta.to.shared.u64 t, %1; cvt.u32.u64 %0, t; }" : "=r"(a) : "l"(p));
    return a;
}
__device__ __forceinline__ void ldsm4(uint32_t* r, uint32_t a){
    asm volatile("ldmatrix.sync.aligned.m8n8.x4.shared.b16 {%0,%1,%2,%3}, [%4];"
        : "=r"(r[0]), "=r"(r[1]), "=r"(r[2]), "=r"(r[3]) : "r"(a));
}
__device__ __forceinline__ void mma16816(float* c, const uint32_t* a, const uint32_t* b){
    asm volatile("mma.sync.aligned.m16n8k16.row.col.f32.f16.f16.f32 "
        "{%0,%1,%2,%3}, {%4,%5,%6,%7}, {%8,%9}, {%0,%1,%2,%3};"
        : "+f"(c[0]), "+f"(c[1]), "+f"(c[2]), "+f"(c[3])
        : "r"(a[0]), "r"(a[1]), "r"(a[2]), "r"(a[3]), "r"(b[0]), "r"(b[1]));
}
// per-strip barrier: 4 warps (128 threads), ids 1..4
#define BARS(id) asm volatile("bar.sync %0, %1;" :: "r"(id), "r"(128) : "memory")
#define CP_COMMIT() asm volatile("cp.async.commit_group;" ::: "memory")
#define CP_WAIT()   asm volatile("cp.async.wait_group 0;" ::: "memory")

__device__ __forceinline__ float ex2f(float v){ float r; asm("ex2.approx.f32 %0, %1;" : "=f"(r) : "f"(v)); return r; }
__device__ __forceinline__ float rcpf(float v){ float r; asm("rcp.approx.f32 %0, %1;" : "=f"(r) : "f"(v)); return r; }
__device__ __forceinline__ float fsigmoid(float v){ return rcpf(1.0f + ex2f(-LOG2E * v)); }
__device__ __forceinline__ float fgelu(float v){
    float u = 0.7978845608028654f * v * (1.0f + 0.044715f * v * v);
    return v - v * rcpf(1.0f + ex2f(2.8853900817779268f * u));
}
__device__ __forceinline__ uint32_t packh(float a, float b){
    __half2 h = __floats2half2_rn(a, b);
    return *(uint32_t*)&h;
}
// store 8 consecutive k-values (fp16) of one row: one 16B swizzle unit
__device__ __forceinline__ void store8h(char* sm, uint32_t base, uint32_t o0, const float* f){
    uint4 v = make_uint4(packh(f[0], f[1]), packh(f[2], f[3]),
                         packh(f[4], f[5]), packh(f[6], f[7]));
    *(uint4*)(sm + base + sw128(o0)) = v;
}

// scratch layout: row = [zone A: 16 granules at 16c+16(c>>3), 272B] [zone B: 48 granules, 784B]
__device__ __forceinline__ uint32_t scr_off(int c){
    if (c < 16) return (uint32_t)(16*c + ((c >> 3) << 4));
    int cc = c - 16;
    int qq = cc / 6;
    int tt = cc - 6*qq;
    return (uint32_t)(272 + 96*qq + 16*tt + ((qq >> 2) << 4));
}
// coalesced async copy of one 1KB x-row into padded scratch (8 x 16B per lane)
__device__ __forceinline__ void cp_x_row(uint32_t scrRow, const char* gRow, int chBase){
    #pragma unroll
    for (int m = 0; m < 8; m++){
        int c = chBase + 8*m;
        uint32_t d = scrRow + scr_off(c);
        asm volatile("cp.async.cg.shared.global [%0], [%1], 16;"
            :: "r"(d), "l"(gRow + (size_t)c * 16) : "memory");
    }
}

// deinterleave one row's scratch -> fp16 slices (X0..X3, E)
__device__ __forceinline__ void cvt_from_scratch(char* sm, uint32_t scrOff, int q,
                                                 float4 yv, uint32_t slBase, uint32_t o0){
    const char* scr = sm + scrOff;
    const uint32_t qg = (uint32_t)((q >> 2) << 4);
    float f[8];
    #pragma unroll
    for (int j = 0; j < 2; j++){
        float4 v = *(const float4*)(scr + 32*q + 16*j + qg);
        f[4*j] = v.x; f[4*j+1] = v.y; f[4*j+2] = v.z; f[4*j+3] = v.w;
    }
    store8h(sm, slBase, o0, f);
    float b[24];
    #pragma unroll
    for (int t = 0; t < 6; t++){
        float4 v = *(const float4*)(scr + 272 + 96*q + 16*t + qg);
        b[4*t] = v.x; b[4*t+1] = v.y; b[4*t+2] = v.z; b[4*t+3] = v.w;
    }
    float f1[8], f2[8], f3[8], fe[8];
    #pragma unroll
    for (int k = 0; k < 8; k++){
        f1[k] = b[3*k]; f2[k] = b[3*k+1]; f3[k] = b[3*k+2];
        fe[k] = IS3 * (yv.y * f1[k] + yv.z * f2[k] + yv.w * f3[k]);
    }
    store8h(sm, slBase +  8192u, o0, f1);
    store8h(sm, slBase + 16384u, o0, f2);
    store8h(sm, slBase + 24576u, o0, f3);
    store8h(sm, slBase + 32768u, o0, fe);
}

__global__ void __launch_bounds__(THREADS, 1)
tpl_mma_kernel(const float* __restrict__ x, const float* __restrict__ y,
               const float* __restrict__ W0, const float* __restrict__ b0,
               const float* __restrict__ W1, float* __restrict__ out)
{
    extern __shared__ char sm[];
    const uint32_t smb = smem_u32(sm);
    const int tid = threadIdx.x, lane = tid & 31, w = tid >> 5;
    const int rs = w & 3;            // row strip (16 rows)
    const int h  = w >> 2;           // N quarter (0..3)
    const int gid = lane >> 2, tig = lane & 3;

    // ---------------- stage weights (fp16, transposed, SW128) ----------------
    for (int idx = tid; idx < 16384; idx += THREADS){
        int c = idx >> 7, o = idx & 127;
        float v = __ldg(W0 + idx);
        uint32_t base = (c < 64) ? OFF_W0A : OFF_W0B;
        uint32_t off = sw128((uint32_t)o * 128u + (uint32_t)(c & 63) * 2u);
        *(__half*)(sm + base + off) = __float2half_rn(v);
    }
    for (int idx = tid; idx < 8192; idx += THREADS){
        int c = idx >> 6, o = idx & 63;
        float v = __ldg(W1 + idx);
        uint32_t base = (c < 64) ? OFF_W1A : OFF_W1B;
        uint32_t off = sw128((uint32_t)o * 128u + (uint32_t)(c & 63) * 2u);
        *(__half*)(sm + base + off) = __float2half_rn(v);
    }

    // ---------------- per-lane ldmatrix offsets ----------------
    const uint32_t aOff = (uint32_t)(rs * 16 + (lane & 15)) * 128u
                        + (((uint32_t)lane >> 4) & 1u) * 16u;
    const uint32_t bK    = (((uint32_t)lane >> 3) & 1u) * 16u;
    const uint32_t bLnO  = (uint32_t)(lane & 7) + (((uint32_t)lane >> 4) & 1u) * 8u;
    // phase A column blocks: p=0 -> gates (h*16), p=1 -> scalars (64 + h*16)
    uint32_t bOffA[2];
    bOffA[0] = ((uint32_t)(h * 16)      + bLnO) * 128u + bK;
    bOffA[1] = ((uint32_t)(64 + h * 16) + bLnO) * 128u + bK;
    const uint32_t bOffB = ((uint32_t)(h * 16) + bLnO) * 128u + bK;

    // b0 values this thread will ever need (4 col-pairs)
    float bA[4], bB[4];
    #pragma unroll
    for (int nb = 0; nb < 4; nb++){
        int col = (nb < 2 ? h * 16 + nb * 8 : 64 + h * 16 + (nb - 2) * 8) + 2 * tig;
        float2 t = __ldg((const float2*)(b0 + col));
        bA[nb] = t.x; bB[nb] = t.y;
    }

    // convert mapping: strip's 4 warps convert 16 rows, 8 threads/row
    const int cr = rs * 16 + h * 4 + (lane >> 3);  // row within tile
    const int q  = lane & 7;                        // col-eighth
    const uint32_t cvtO = (uint32_t)cr * 128u + (uint32_t)q * 16u;
    const uint32_t scrRowOff = OFF_SCR + (uint32_t)w * SCR_WARP + (uint32_t)(lane >> 3) * SCR_ROW;
    const uint32_t scrRowAddr = smb + scrRowOff;
    const int chBase = lane & 7;
    const int barid = rs + 1;
    const int grid = gridDim.x;

    __syncthreads();   // weights staged

    // cache pass-2 B fragments (tile-invariant) in registers
    uint32_t B2c[4][4];
    #pragma unroll
    for (int ks = 0; ks < 4; ks++)
        ldsm4(B2c[ks], smb + OFF_W1B + sw128(bOffB + (uint32_t)ks * 32u));

    // ---------------- prologue: stage + convert first tile into buffer 0 ----------------
    cp_x_row(scrRowAddr, (const char*)x + (size_t)(blockIdx.x * 64 + cr) * 1024, chBase);
    CP_COMMIT();
    {
        float4 yv0 = __ldg((const float4*)(y + (size_t)(blockIdx.x * 64 + cr) * 4));
        CP_WAIT(); __syncwarp();
        cvt_from_scratch(sm, scrRowOff, q, yv0, OFF_SL, cvtO);
    }
    BARS(barid);

    uint32_t bufc = 0;
    for (int tile = blockIdx.x; tile < NTILES; tile += grid, bufc ^= 1){
        const int n0 = tile * 64;
        const int nxt = tile + grid;
        const bool hasNext = nxt < NTILES;
        const uint32_t cbase = OFF_SL + bufc * SLBUF;

        // -------- async-stage next tile's x (hides LDG under MMAs, no registers) --------
        float4 yv_nx;
        if (hasNext){
            cp_x_row(scrRowAddr, (const char*)x + (size_t)(nxt * 64 + cr) * 1024, chBase);
            CP_COMMIT();
            yv_nx = __ldg((const float4*)(y + (size_t)(nxt * 64 + cr) * 4));
        }

        // per-fragment-row y coefficients
        const int gr0 = n0 + rs * 16 + gid, gr1 = gr0 + 8;
        const float4 y0v = __ldg((const float4*)(y + (size_t)gr0 * 4));
        const float4 y1v = __ldg((const float4*)(y + (size_t)gr1 * 4));

        // ---------------- fused pass 1: X0@W0a (S) + X0@W1a (P) ----------------
        float S[4][4], P[2][4];
        #pragma unroll
        for (int nb = 0; nb < 4; nb++){ S[nb][0]=0.f; S[nb][1]=0.f; S[nb][2]=0.f; S[nb][3]=0.f; }
        #pragma unroll
        for (int nb = 0; nb < 2; nb++){ P[nb][0]=0.f; P[nb][1]=0.f; P[nb][2]=0.f; P[nb][3]=0.f; }

        #pragma unroll
        for (int ks = 0; ks < 4; ks++){
            uint32_t A[4];
            ldsm4(A, smb + cbase + sw128(aOff + (uint32_t)ks * 32u));
            #pragma unroll
            for (int p = 0; p < 2; p++){
                uint32_t B[4];
                ldsm4(B, smb + OFF_W0A + sw128(bOffA[p] + (uint32_t)ks * 32u));
                mma16816(S[2*p],     A, B);
                mma16816(S[2*p + 1], A, B + 2);
            }
            {
                uint32_t B[4];
                ldsm4(B, smb + OFF_W1A + sw128(bOffB + (uint32_t)ks * 32u));
                mma16816(P[0], A, B);
                mma16816(P[1], A, B + 2);
            }
        }

        // scale S by per-row y0, then add E@W0b
        #pragma unroll
        for (int nb = 0; nb < 4; nb++){
            S[nb][0] *= y0v.x; S[nb][1] *= y0v.x;
            S[nb][2] *= y1v.x; S[nb][3] *= y1v.x;
        }
        #pragma unroll
        for (int ks = 0; ks < 4; ks++){
            uint32_t A[4];
            ldsm4(A, smb + cbase + 32768u + sw128(aOff + (uint32_t)ks * 32u));
            #pragma unroll
            for (int p = 0; p < 2; p++){
                uint32_t B[4];
                ldsm4(B, smb + OFF_W0B + sw128(bOffA[p] + (uint32_t)ks * 32u));
                mma16816(S[2*p],     A, B);
                mma16816(S[2*p + 1], A, B + 2);
            }
        }

        // ---------------- epilogue A: gates -> regs, gelu scalars -> gmem ----------------
        float gown[2][4];
        #pragma unroll
        for (int nb = 0; nb < 2; nb++){
            gown[nb][0] = fsigmoid(S[nb][0] * ISF + bA[nb]);
            gown[nb][1] = fsigmoid(S[nb][1] * ISF + bB[nb]);
            gown[nb][2] = fsigmoid(S[nb][2] * ISF + bA[nb]);
            gown[nb][3] = fsigmoid(S[nb][3] * ISF + bB[nb]);
        }
        #pragma unroll
        for (int nb = 2; nb < 4; nb++){
            const int c0 = h * 16 + (nb - 2) * 8 + 2 * tig;   // out scalar col
            float2 e0 = { fgelu(S[nb][0] * ISF + bA[nb]), fgelu(S[nb][1] * ISF + bB[nb]) };
            float2 e1 = { fgelu(S[nb][2] * ISF + bA[nb]), fgelu(S[nb][3] * ISF + bB[nb]) };
            *(float2*)(out + (size_t)gr0 * 256 + c0) = e0;
            *(float2*)(out + (size_t)gr1 * 256 + c0) = e1;
        }

        // ---------------- pass 2: Q_i = X_i@W1b (B frags cached in registers) ----------------
        float Q[3][2][4];
        #pragma unroll
        for (int i = 0; i < 3; i++)
            #pragma unroll
            for (int nb = 0; nb < 2; nb++){ Q[i][nb][0]=0.f; Q[i][nb][1]=0.f; Q[i][nb][2]=0.f; Q[i][nb][3]=0.f; }

        #pragma unroll
        for (int ks = 0; ks < 4; ks++){
            const uint32_t ao = sw128(aOff + (uint32_t)ks * 32u);
            uint32_t A[3][4];
            #pragma unroll
            for (int i = 0; i < 3; i++)
                ldsm4(A[i], smb + cbase + 8192u * (1 + i) + ao);
            #pragma unroll
            for (int i = 0; i < 3; i++){
                mma16816(Q[i][0], A[i], B2c[ks]);
                mma16816(Q[i][1], A[i], B2c[ks] + 2);
            }
        }

        // -------- deinterleave staged x(t+1) -> other slice buffer, then barrier --------
        if (hasNext){
            CP_WAIT(); __syncwarp();
            cvt_from_scratch(sm, scrRowOff, q, yv_nx, OFF_SL + (bufc ^ 1u) * SLBUF, cvtO);
        }
        BARS(barid);   // next slices ready AND this tile's slice reads complete

        // ---------------- epilogue B (registers + STG only) ----------------
        {
            const float c0r0 = y0v.x * ISF, c0r1 = y1v.x * ISF;
            #pragma unroll
            for (int nb = 0; nb < 2; nb++){
                const int cB = h * 16 + nb * 8 + 2 * tig;
                float2 ga = { gown[nb][0], gown[nb][1] };
                float2 gb = { gown[nb][2], gown[nb][3] };
                float vo[3][4];
                #pragma unroll
                for (int i = 0; i < 3; i++){
                    const float c1r0 = (&y0v.x)[1 + i] * ISF, c1r1 = (&y1v.x)[1 + i] * ISF;
                    vo[i][0] = c1r0 * P[nb][0] + c0r0 * Q[i][nb][0];
                    vo[i][1] = c1r0 * P[nb][1] + c0r0 * Q[i][nb][1];
                    vo[i][2] = c1r1 * P[nb][2] + c0r1 * Q[i][nb][2];
                    vo[i][3] = c1r1 * P[nb][3] + c0r1 * Q[i][nb][3];
                }
                float* o0p = out + (size_t)gr0 * 256 + 64 + 3 * cB;
                float* o1p = out + (size_t)gr1 * 256 + 64 + 3 * cB;
                float2 t;
                t.x = ga.x * vo[0][0]; t.y = ga.x * vo[1][0]; *(float2*)(o0p)     = t;
                t.x = ga.x * vo[2][0]; t.y = ga.y * vo[0][1]; *(float2*)(o0p + 2) = t;
                t.x = ga.y * vo[1][1]; t.y = ga.y * vo[2][1]; *(float2*)(o0p + 4) = t;
                t.x = gb.x * vo[0][2]; t.y = gb.x * vo[1][2]; *(float2*)(o1p)     = t;
                t.x = gb.x * vo[2][2]; t.y = gb.y * vo[0][3]; *(float2*)(o1p + 2) = t;
                t.x = gb.y * vo[1][3]; t.y = gb.y * vo[2][3]; *(float2*)(o1p + 4) = t;
            }
        }
    }
}

extern "C" void kernel_launch(void* const* d_in, const int* in_sizes, int n_in,
                              void* d_out, int out_size)
{
    (void)in_sizes; (void)n_in; (void)out_size;
    const float* x  = (const float*)d_in[0];
    const float* y  = (const float*)d_in[1];
    const float* W0 = (const float*)d_in[2];
    const float* b0 = (const float*)d_in[3];
    const float* W1 = (const float*)d_in[4];
    float* out = (float*)d_out;

    cudaFuncSetAttribute(tpl_mma_kernel,
                         cudaFuncAttributeMaxDynamicSharedMemorySize, SMEM_BYTES);

    int dev = 0;
    cudaGetDevice(&dev);
    int sms = 148;
    cudaDeviceGetAttribute(&sms, cudaDevAttrMultiProcessorCount, dev);
    int grid = sms < NTILES ? sms : NTILES;

    tpl_mma_kernel<<<grid, THREADS, SMEM_BYTES>>>(x, y, W0, b0, W1, out);
}

// round 14
// speedup vs baseline: 1.0526x; 1.0526x over previous
#include <cuda_runtime.h>
#include <cuda_fp16.h>
#include <cstdint>

#define THREADS 512
#define NTILES  2048          // 131072 / 64 rows

#define ISF   0.08838834764831845f
#define IS3   0.5773502691896258f
#define LOG2E 1.4426950408889634f

// ---------------- smem byte offsets ----------------
// two slice buffers (fp16): each 5 slices (X0..X3, E) x 8KB = 40KB
#define OFF_SL   0u
#define SLBUF    40960u
#define OFF_W0A  81920u       // W0[0:64,:]^T  [o:128][k:64] fp16, 16KB
#define OFF_W0B  98304u       // W0[64:128,:]^T
#define OFF_W1A  114688u      // W1[0:64,:]^T  [o:64][k:64] fp16, 8KB
#define OFF_W1B  122880u      // W1[64:128,:]^T
#define SMEM_BYTES 131072

__device__ __forceinline__ uint32_t sw128(uint32_t o){ return o ^ ((o >> 3) & 0x70); }
__device__ __forceinline__ uint32_t smem_u32(const void* p){
    uint32_t a;
    asm("{ .reg .u64 t; cvta.to.shared.u64 t, %1; cvt.u32.u64 %0, t; }" : "=r"(a) : "l"(p));
    return a;
}
__device__ __forceinline__ void ldsm4(uint32_t* r, uint32_t a){
    asm volatile("ldmatrix.sync.aligned.m8n8.x4.shared.b16 {%0,%1,%2,%3}, [%4];"
        : "=r"(r[0]), "=r"(r[1]), "=r"(r[2]), "=r"(r[3]) : "r"(a));
}
__device__ __forceinline__ void mma16816(float* c, const uint32_t* a, const uint32_t* b){
    asm volatile("mma.sync.aligned.m16n8k16.row.col.f32.f16.f16.f32 "
        "{%0,%1,%2,%3}, {%4,%5,%6,%7}, {%8,%9}, {%0,%1,%2,%3};"
        : "+f"(c[0]), "+f"(c[1]), "+f"(c[2]), "+f"(c[3])
        : "r"(a[0]), "r"(a[1]), "r"(a[2]), "r"(a[3]), "r"(b[0]), "r"(b[1]));
}
__device__ __forceinline__ uint32_t prmt(uint32_t a, uint32_t b, uint32_t sel){
    uint32_t r; asm("prmt.b32 %0, %1, %2, %3;" : "=r"(r) : "r"(a), "r"(b), "r"(sel));
    return r;
}
// per-strip barrier: 4 warps (128 threads), ids 1..4
#define BARS(id) asm volatile("bar.sync %0, %1;" :: "r"(id), "r"(128) : "memory")

__device__ __forceinline__ float ex2f(float v){ float r; asm("ex2.approx.f32 %0, %1;" : "=f"(r) : "f"(v)); return r; }
__device__ __forceinline__ float rcpf(float v){ float r; asm("rcp.approx.f32 %0, %1;" : "=f"(r) : "f"(v)); return r; }
__device__ __forceinline__ float fsigmoid(float v){ return rcpf(1.0f + ex2f(-LOG2E * v)); }
__device__ __forceinline__ float fgelu(float v){
    float u = 0.7978845608028654f * v * (1.0f + 0.044715f * v * v);
    return v - v * rcpf(1.0f + ex2f(2.8853900817779268f * u));
}
__device__ __forceinline__ uint32_t packh(float a, float b){
    __half2 h = __floats2half2_rn(a, b);
    return *(uint32_t*)&h;
}

// ---- x prefetch: packed fp16 in registers (20 regs incl. yv) ----
struct XPreP { uint32_t a[4]; uint32_t b[12]; float4 yv; };

__device__ __forceinline__ void ldxp(const float* __restrict__ x,
                                     const float* __restrict__ y,
                                     int row, int q, XPreP& p){
    const float* xr = x + (size_t)row * 256;
    p.yv = __ldg((const float4*)(y + (size_t)row * 4));
    #pragma unroll
    for (int j = 0; j < 2; j++){
        float4 v = __ldg((const float4*)xr + q * 2 + j);
        p.a[2*j]   = packh(v.x, v.y);
        p.a[2*j+1] = packh(v.z, v.w);
    }
    #pragma unroll
    for (int j = 0; j < 6; j++){
        float4 v = __ldg((const float4*)xr + 16 + q * 6 + j);
        p.b[2*j]   = packh(v.x, v.y);
        p.b[2*j+1] = packh(v.z, v.w);
    }
}

// deinterleave packed zone-B + build E (half2 math), store all 5 slices
__device__ __forceinline__ void stxp(char* sm, uint32_t base, uint32_t o0, const XPreP& p){
    *(uint4*)(sm + base + sw128(o0)) = make_uint4(p.a[0], p.a[1], p.a[2], p.a[3]);

    uint32_t f1u[4], f2u[4], f3u[4], feu[4];
    f1u[0] = prmt(p.b[0], p.b[1],  0x7610); f1u[1] = prmt(p.b[3], p.b[4],  0x7610);
    f1u[2] = prmt(p.b[6], p.b[7],  0x7610); f1u[3] = prmt(p.b[9], p.b[10], 0x7610);
    f2u[0] = prmt(p.b[0], p.b[2],  0x5432); f2u[1] = prmt(p.b[3], p.b[5],  0x5432);
    f2u[2] = prmt(p.b[6], p.b[8],  0x5432); f2u[3] = prmt(p.b[9], p.b[11], 0x5432);
    f3u[0] = prmt(p.b[1], p.b[2],  0x7610); f3u[1] = prmt(p.b[4], p.b[5],  0x7610);
    f3u[2] = prmt(p.b[7], p.b[8],  0x7610); f3u[3] = prmt(p.b[10], p.b[11],0x7610);

    __half2 c1 = __float2half2_rn(IS3 * p.yv.y);
    __half2 c2 = __float2half2_rn(IS3 * p.yv.z);
    __half2 c3 = __float2half2_rn(IS3 * p.yv.w);
    #pragma unroll
    for (int j = 0; j < 4; j++){
        __half2 e = __hfma2(c3, *(__half2*)&f3u[j],
                    __hfma2(c2, *(__half2*)&f2u[j],
                    __hmul2(c1, *(__half2*)&f1u[j])));
        feu[j] = *(uint32_t*)&e;
    }
    *(uint4*)(sm + base +  8192u + sw128(o0)) = make_uint4(f1u[0], f1u[1], f1u[2], f1u[3]);
    *(uint4*)(sm + base + 16384u + sw128(o0)) = make_uint4(f2u[0], f2u[1], f2u[2], f2u[3]);
    *(uint4*)(sm + base + 24576u + sw128(o0)) = make_uint4(f3u[0], f3u[1], f3u[2], f3u[3]);
    *(uint4*)(sm + base + 32768u + sw128(o0)) = make_uint4(feu[0], feu[1], feu[2], feu[3]);
}

__global__ void __launch_bounds__(THREADS, 1)
tpl_mma_kernel(const float* __restrict__ x, const float* __restrict__ y,
               const float* __restrict__ W0, const float* __restrict__ b0,
               const float* __restrict__ W1, float* __restrict__ out)
{
    extern __shared__ char sm[];
    const uint32_t smb = smem_u32(sm);
    const int tid = threadIdx.x, lane = tid & 31, w = tid >> 5;
    const int rs = w & 3;            // row strip (16 rows)
    const int h  = w >> 2;           // N quarter (0..3)
    const int gid = lane >> 2, tig = lane & 3;

    // ---------------- stage weights (fp16, transposed, SW128) ----------------
    for (int idx = tid; idx < 16384; idx += THREADS){
        int c = idx >> 7, o = idx & 127;
        float v = __ldg(W0 + idx);
        uint32_t base = (c < 64) ? OFF_W0A : OFF_W0B;
        uint32_t off = sw128((uint32_t)o * 128u + (uint32_t)(c & 63) * 2u);
        *(__half*)(sm + base + off) = __float2half_rn(v);
    }
    for (int idx = tid; idx < 8192; idx += THREADS){
        int c = idx >> 6, o = idx & 63;
        float v = __ldg(W1 + idx);
        uint32_t base = (c < 64) ? OFF_W1A : OFF_W1B;
        uint32_t off = sw128((uint32_t)o * 128u + (uint32_t)(c & 63) * 2u);
        *(__half*)(sm + base + off) = __float2half_rn(v);
    }

    // ---------------- per-lane ldmatrix offsets ----------------
    const uint32_t aOff = (uint32_t)(rs * 16 + (lane & 15)) * 128u
                        + (((uint32_t)lane >> 4) & 1u) * 16u;
    const uint32_t bK    = (((uint32_t)lane >> 3) & 1u) * 16u;
    const uint32_t bLnO  = (uint32_t)(lane & 7) + (((uint32_t)lane >> 4) & 1u) * 8u;
    // phase A column blocks: p=0 -> gates (h*16), p=1 -> scalars (64 + h*16)
    uint32_t bOffA[2];
    bOffA[0] = ((uint32_t)(h * 16)      + bLnO) * 128u + bK;
    bOffA[1] = ((uint32_t)(64 + h * 16) + bLnO) * 128u + bK;
    const uint32_t bOffB = ((uint32_t)(h * 16) + bLnO) * 128u + bK;

    // b0 values this thread will ever need (4 col-pairs)
    float bA[4], bB[4];
    #pragma unroll
    for (int nb = 0; nb < 4; nb++){
        int col = (nb < 2 ? h * 16 + nb * 8 : 64 + h * 16 + (nb - 2) * 8) + 2 * tig;
        float2 t = __ldg((const float2*)(b0 + col));
        bA[nb] = t.x; bB[nb] = t.y;
    }

    // convert mapping: strip's 4 warps convert 16 rows, 8 threads/row, 32 cols/thread
    const int cr = rs * 16 + h * 4 + (lane >> 3);  // row within tile
    const int q  = lane & 7;                        // col-eighth
    const uint32_t cvtO = (uint32_t)cr * 128u + (uint32_t)q * 16u;
    const int barid = rs + 1;
    const int grid = gridDim.x;

    __syncthreads();   // weights staged

    // cache pass-2 B fragments (tile-invariant) in registers
    uint32_t B2c[4][4];
    #pragma unroll
    for (int ks = 0; ks < 4; ks++)
        ldsm4(B2c[ks], smb + OFF_W1B + sw128(bOffB + (uint32_t)ks * 32u));

    // ---------------- prologue: convert first tile into buffer 0 ----------------
    {
        XPreP p0;
        ldxp(x, y, blockIdx.x * 64 + cr, q, p0);
        stxp(sm, OFF_SL, cvtO, p0);
    }
    BARS(barid);

    uint32_t bufc = 0;
    for (int tile = blockIdx.x; tile < NTILES; tile += grid, bufc ^= 1){
        const int n0 = tile * 64;
        const int nxt = tile + grid;
        const bool hasNext = nxt < NTILES;
        const uint32_t cbase = OFF_SL + bufc * SLBUF;

        // -------- prefetch next tile's x into packed registers --------
        XPreP pf;
        if (hasNext) ldxp(x, y, nxt * 64 + cr, q, pf);

        // per-fragment-row y coefficients
        const int gr0 = n0 + rs * 16 + gid, gr1 = gr0 + 8;
        const float4 y0v = __ldg((const float4*)(y + (size_t)gr0 * 4));
        const float4 y1v = __ldg((const float4*)(y + (size_t)gr1 * 4));

        // ---------------- fused pass 1: X0@W0a (S) + X0@W1a (P) ----------------
        float S[4][4], P[2][4];
        #pragma unroll
        for (int nb = 0; nb < 4; nb++){ S[nb][0]=0.f; S[nb][1]=0.f; S[nb][2]=0.f; S[nb][3]=0.f; }
        #pragma unroll
        for (int nb = 0; nb < 2; nb++){ P[nb][0]=0.f; P[nb][1]=0.f; P[nb][2]=0.f; P[nb][3]=0.f; }

        #pragma unroll
        for (int ks = 0; ks < 4; ks++){
            uint32_t A[4];
            ldsm4(A, smb + cbase + sw128(aOff + (uint32_t)ks * 32u));
            #pragma unroll
            for (int p = 0; p < 2; p++){
                uint32_t B[4];
                ldsm4(B, smb + OFF_W0A + sw128(bOffA[p] + (uint32_t)ks * 32u));
                mma16816(S[2*p],     A, B);
                mma16816(S[2*p + 1], A, B + 2);
            }
            {
                uint32_t B[4];
                ldsm4(B, smb + OFF_W1A + sw128(bOffB + (uint32_t)ks * 32u));
                mma16816(P[0], A, B);
                mma16816(P[1], A, B + 2);
            }
        }

        // scale S by per-row y0, then add E@W0b
        #pragma unroll
        for (int nb = 0; nb < 4; nb++){
            S[nb][0] *= y0v.x; S[nb][1] *= y0v.x;
            S[nb][2] *= y1v.x; S[nb][3] *= y1v.x;
        }
        #pragma unroll
        for (int ks = 0; ks < 4; ks++){
            uint32_t A[4];
            ldsm4(A, smb + cbase + 32768u + sw128(aOff + (uint32_t)ks * 32u));
            #pragma unroll
            for (int p = 0; p < 2; p++){
                uint32_t B[4];
                ldsm4(B, smb + OFF_W0B + sw128(bOffA[p] + (uint32_t)ks * 32u));
                mma16816(S[2*p],     A, B);
                mma16816(S[2*p + 1], A, B + 2);
            }
        }

        // ---------------- epilogue A: gates -> regs, gelu scalars -> gmem ----------------
        float gown[2][4];
        #pragma unroll
        for (int nb = 0; nb < 2; nb++){
            gown[nb][0] = fsigmoid(S[nb][0] * ISF + bA[nb]);
            gown[nb][1] = fsigmoid(S[nb][1] * ISF + bB[nb]);
            gown[nb][2] = fsigmoid(S[nb][2] * ISF + bA[nb]);
            gown[nb][3] = fsigmoid(S[nb][3] * ISF + bB[nb]);
        }
        #pragma unroll
        for (int nb = 2; nb < 4; nb++){
            const int c0 = h * 16 + (nb - 2) * 8 + 2 * tig;   // out scalar col
            float2 e0 = { fgelu(S[nb][0] * ISF + bA[nb]), fgelu(S[nb][1] * ISF + bB[nb]) };
            float2 e1 = { fgelu(S[nb][2] * ISF + bA[nb]), fgelu(S[nb][3] * ISF + bB[nb]) };
            *(float2*)(out + (size_t)gr0 * 256 + c0) = e0;
            *(float2*)(out + (size_t)gr1 * 256 + c0) = e1;
        }

        // ---------------- pass 2: Q_i = X_i@W1b (B frags cached in registers) ----------------
        float Q[3][2][4];
        #pragma unroll
        for (int i = 0; i < 3; i++)
            #pragma unroll
            for (int nb = 0; nb < 2; nb++){ Q[i][nb][0]=0.f; Q[i][nb][1]=0.f; Q[i][nb][2]=0.f; Q[i][nb][3]=0.f; }

        #pragma unroll
        for (int ks = 0; ks < 4; ks++){
            const uint32_t ao = sw128(aOff + (uint32_t)ks * 32u);
            uint32_t A[3][4];
            #pragma unroll
            for (int i = 0; i < 3; i++)
                ldsm4(A[i], smb + cbase + 8192u * (1 + i) + ao);
            #pragma unroll
            for (int i = 0; i < 3; i++){
                mma16816(Q[i][0], A[i], B2c[ks]);
                mma16816(Q[i][1], A[i], B2c[ks] + 2);
            }
        }

        // -------- convert/store next tile into the other buffer, then barrier --------
        if (hasNext) stxp(sm, OFF_SL + (bufc ^ 1u) * SLBUF, cvtO, pf);
        BARS(barid);   // next slices ready AND this tile's slice reads complete

        // ---------------- epilogue B (registers + STG only) ----------------
        {
            const float c0r0 = y0v.x * ISF, c0r1 = y1v.x * ISF;
            #pragma unroll
            for (int nb = 0; nb < 2; nb++){
                const int cB = h * 16 + nb * 8 + 2 * tig;
                float2 ga = { gown[nb][0], gown[nb][1] };
                float2 gb = { gown[nb][2], gown[nb][3] };
                float vo[3][4];
                #pragma unroll
                for (int i = 0; i < 3; i++){
                    const float c1r0 = (&y0v.x)[1 + i] * ISF, c1r1 = (&y1v.x)[1 + i] * ISF;
                    vo[i][0] = c1r0 * P[nb][0] + c0r0 * Q[i][nb][0];
                    vo[i][1] = c1r0 * P[nb][1] + c0r0 * Q[i][nb][1];
                    vo[i][2] = c1r1 * P[nb][2] + c0r1 * Q[i][nb][2];
                    vo[i][3] = c1r1 * P[nb][3] + c0r1 * Q[i][nb][3];
                }
                float* o0p = out + (size_t)gr0 * 256 + 64 + 3 * cB;
                float* o1p = out + (size_t)gr1 * 256 + 64 + 3 * cB;
                float2 t;
                t.x = ga.x * vo[0][0]; t.y = ga.x * vo[1][0]; *(float2*)(o0p)     = t;
                t.x = ga.x * vo[2][0]; t.y = ga.y * vo[0][1]; *(float2*)(o0p + 2) = t;
                t.x = ga.y * vo[1][1]; t.y = ga.y * vo[2][1]; *(float2*)(o0p + 4) = t;
                t.x = gb.x * vo[0][2]; t.y = gb.x * vo[1][2]; *(float2*)(o1p)     = t;
                t.x = gb.x * vo[2][2]; t.y = gb.y * vo[0][3]; *(float2*)(o1p + 2) = t;
                t.x = gb.y * vo[1][3]; t.y = gb.y * vo[2][3]; *(float2*)(o1p + 4) = t;
            }
        }
    }
}

extern "C" void kernel_launch(void* const* d_in, const int* in_sizes, int n_in,
                              void* d_out, int out_size)
{
    (void)in_sizes; (void)n_in; (void)out_size;
    const float* x  = (const float*)d_in[0];
    const float* y  = (const float*)d_in[1];
    const float* W0 = (const float*)d_in[2];
    const float* b0 = (const float*)d_in[3];
    const float* W1 = (const float*)d_in[4];
    float* out = (float*)d_out;

    cudaFuncSetAttribute(tpl_mma_kernel,
                         cudaFuncAttributeMaxDynamicSharedMemorySize, SMEM_BYTES);

    int dev = 0;
    cudaGetDevice(&dev);
    int sms = 148;
    cudaDeviceGetAttribute(&sms, cudaDevAttrMultiProcessorCount, dev);
    int grid = sms < NTILES ? sms : NTILES;

    tpl_mma_kernel<<<grid, THREADS, SMEM_BYTES>>>(x, y, W0, b0, W1, out);
}